// round 5
// baseline (speedup 1.0000x reference)
#include <cuda_runtime.h>
#include <cuda_bf16.h>
#include <math.h>

#define BB 256
#define HH 512
#define CC 512
#define NL 128
#define TT 23
#define LSEQ 24
#define VV 64
#define BH (BB*HH)
#define NTOK (TT*BB)
#define KT 8

typedef unsigned long long u64;

__device__ __forceinline__ void FMA2(u64 &d, u64 a, u64 b){
  asm("fma.rn.f32x2 %0, %1, %2, %0;" : "+l"(d) : "l"(a), "l"(b));
}
__device__ __forceinline__ u64 PACK2(float x, float y){
  u64 r; asm("mov.b64 %0, {%1, %2};" : "=l"(r) : "f"(x), "f"(y)); return r;
}
__device__ __forceinline__ float2 UNPK(u64 v){
  float2 r; asm("mov.b64 {%0, %1}, %2;" : "=f"(r.x), "=f"(r.y) : "l"(v)); return r;
}

// ---------------- static scratch ----------------
__device__ __nv_bfloat16 g_Wsh[(size_t)BB*NL*HH];
__device__ __nv_bfloat16 g_ench[(size_t)BB*CC*NL];
__device__ float g_xg[(size_t)TT*BB*3*HH];
__device__ float g_xs[(size_t)TT*BH];
__device__ float g_ys[(size_t)TT*BH];
__device__ float g_y0[BH];
__device__ float g_h0buf[2][BH];
__device__ float g_h1buf[2][BH];
__device__ float g_gp[6][(size_t)BB*3*HH];   // gate GEMM partials (6 z-slices)
__device__ float g_fp[16][BH];               // fc partials
__device__ float g_Up[16][BH];               // Uh partials
__device__ float g_ctx[BH];
__device__ float g_lg[2][(size_t)NTOK*VV];
__device__ float g_nll[NTOK];
__device__ float g_msk[NTOK];

// ---------------- init hidden states ----------------
__global__ void k_inith(const float* __restrict__ init_state,
                        float* __restrict__ h0, float* __restrict__ h1){
  int idx = blockIdx.x*blockDim.x + threadIdx.x;
  if (idx < BH){
    int j = idx & (HH-1);
    h0[idx] = init_state[j];
    h1[idx] = init_state[HH + j];
  }
}

// ---------------- embedding gather ----------------
__global__ void k_embed(const float* __restrict__ emb, const int* __restrict__ seq,
                        float* __restrict__ xs){
  int idx = blockIdx.x*blockDim.x + threadIdx.x;
  if (idx < TT*BH){
    int h = idx & (HH-1);
    int r = idx >> 9;
    int b = r & (BB-1);
    int t = r >> 8;
    int tok = seq[b*LSEQ + t];
    xs[idx] = emb[(size_t)tok*HH + h];
  }
}

// ---------------- fp32 -> bf16 copy ----------------
__global__ void k_tobf16(const float* __restrict__ in, __nv_bfloat16* __restrict__ out, int n4){
  int idx = blockIdx.x*blockDim.x + threadIdx.x;
  if (idx < n4){
    float4 v = *(const float4*)&in[(size_t)idx*4];
    *(__nv_bfloat162*)&out[(size_t)idx*4]   = __floats2bfloat162_rn(v.x, v.y);
    *(__nv_bfloat162*)&out[(size_t)idx*4+2] = __floats2bfloat162_rn(v.z, v.w);
  }
}

// ============ 128x128 microkernel core: 8x8/thread, f32x2, splatted W ============
// At: [KT][132] f32 (m-major rows of pairs); WtU: [KT][130] u64 (splatted w)
#define MZ_COMPUTE(buf)                                                     \
  _Pragma("unroll")                                                         \
  for (int kk=0;kk<KT;kk++){                                                \
    ulonglong2 aP = *(const ulonglong2*)&At[buf][kk][tm*8];                 \
    ulonglong2 aQ = *(const ulonglong2*)&At[buf][kk][tm*8+4];               \
    ulonglong2 w01 = *(const ulonglong2*)&WtU[buf][kk][tn*8];               \
    ulonglong2 w23 = *(const ulonglong2*)&WtU[buf][kk][tn*8+2];             \
    ulonglong2 w45 = *(const ulonglong2*)&WtU[buf][kk][tn*8+4];             \
    ulonglong2 w67 = *(const ulonglong2*)&WtU[buf][kk][tn*8+6];             \
    u64 wv0=w01.x, wv1=w01.y, wv2=w23.x, wv3=w23.y;                         \
    u64 wv4=w45.x, wv5=w45.y, wv6=w67.x, wv7=w67.y;                         \
    FMA2(acc[0][0],aP.x,wv0); FMA2(acc[1][0],aP.y,wv0);                     \
    FMA2(acc[2][0],aQ.x,wv0); FMA2(acc[3][0],aQ.y,wv0);                     \
    FMA2(acc[0][1],aP.x,wv1); FMA2(acc[1][1],aP.y,wv1);                     \
    FMA2(acc[2][1],aQ.x,wv1); FMA2(acc[3][1],aQ.y,wv1);                     \
    FMA2(acc[0][2],aP.x,wv2); FMA2(acc[1][2],aP.y,wv2);                     \
    FMA2(acc[2][2],aQ.x,wv2); FMA2(acc[3][2],aQ.y,wv2);                     \
    FMA2(acc[0][3],aP.x,wv3); FMA2(acc[1][3],aP.y,wv3);                     \
    FMA2(acc[2][3],aQ.x,wv3); FMA2(acc[3][3],aQ.y,wv3);                     \
    FMA2(acc[0][4],aP.x,wv4); FMA2(acc[1][4],aP.y,wv4);                     \
    FMA2(acc[2][4],aQ.x,wv4); FMA2(acc[3][4],aQ.y,wv4);                     \
    FMA2(acc[0][5],aP.x,wv5); FMA2(acc[1][5],aP.y,wv5);                     \
    FMA2(acc[2][5],aQ.x,wv5); FMA2(acc[3][5],aQ.y,wv5);                     \
    FMA2(acc[0][6],aP.x,wv6); FMA2(acc[1][6],aP.y,wv6);                     \
    FMA2(acc[2][6],aQ.x,wv6); FMA2(acc[3][6],aQ.y,wv6);                     \
    FMA2(acc[0][7],aP.x,wv7); FMA2(acc[1][7],aP.y,wv7);                     \
    FMA2(acc[2][7],aQ.x,wv7); FMA2(acc[3][7],aQ.y,wv7);                     \
  }

// ---------------- generic 128x128 GEMM with 2 operand sets + K-slicing ----------------
// grid (Mtiles, Ntiles, z). set = z/zPerSet, kb = (z%zPerSet)*kLen, len = min(kLen, K-kb).
// Writes raw partial to Cb + z*M*ldc.
__global__ void __launch_bounds__(256) k_mz(
    const float* __restrict__ A0, int wA0, const float* __restrict__ W0, int s0, int o0,
    const float* __restrict__ A1, int wA1, const float* __restrict__ W1, int s1, int o1,
    int zPerSet, int kLen, int K, float* __restrict__ Cb, int ldc){
  __shared__ __align__(16) float At[2][KT][132];
  __shared__ __align__(16) u64  WtU[2][KT][130];
  int z = blockIdx.z;
  int set = z / zPerSet;
  int kb = (z - set*zPerSet) * kLen;
  int len = min(kLen, K - kb);
  const float* A = set ? A1 : A0;
  const float* W = set ? W1 : W0;
  int wA = set ? wA1 : wA0;
  int s  = set ? s1 : s0;
  int o  = set ? o1 : o0;
  int M = gridDim.x * 128;
  float* C = Cb + (size_t)z * M * ldc;

  int m0 = blockIdx.x*128, n0 = blockIdx.y*128;
  int tid = threadIdx.x;
  int tm = tid & 15, tn = tid >> 4;
  int amm = tid >> 1, ak4 = (tid & 1)*4;
  u64 acc[4][8] = {};
  float4 ra, rw;
  int nt = len / KT;

  auto loadT = [&](int t){
    int kc = kb + t*KT;
    ra = *(const float4*)&A[(size_t)(m0+amm)*wA + kc + ak4];
    rw = *(const float4*)&W[(size_t)(n0+amm)*s + o + kc + ak4];
  };
  auto storeT = [&](int buf){
    At[buf][ak4+0][amm]=ra.x; At[buf][ak4+1][amm]=ra.y;
    At[buf][ak4+2][amm]=ra.z; At[buf][ak4+3][amm]=ra.w;
    WtU[buf][ak4+0][amm]=PACK2(rw.x,rw.x); WtU[buf][ak4+1][amm]=PACK2(rw.y,rw.y);
    WtU[buf][ak4+2][amm]=PACK2(rw.z,rw.z); WtU[buf][ak4+3][amm]=PACK2(rw.w,rw.w);
  };

  loadT(0); storeT(0); __syncthreads();
  for (int t=0;t<nt;t++){
    int buf = t & 1;
    if (t+1 < nt) loadT(t+1);
    MZ_COMPUTE(buf)
    if (t+1 < nt) storeT((t+1)&1);
    __syncthreads();
  }
  #pragma unroll
  for (int p=0;p<4;p++){
    float lo[8], hi[8];
    #pragma unroll
    for (int n=0;n<8;n++){ float2 v = UNPK(acc[p][n]); lo[n]=v.x; hi[n]=v.y; }
    int mA = m0 + tm*8 + p*2;
    float* cA = C + (size_t)mA*ldc + n0 + tn*8;
    float* cB = cA + ldc;
    *(float4*)cA     = make_float4(lo[0],lo[1],lo[2],lo[3]);
    *(float4*)(cA+4) = make_float4(lo[4],lo[5],lo[6],lo[7]);
    *(float4*)cB     = make_float4(hi[0],hi[1],hi[2],hi[3]);
    *(float4*)(cB+4) = make_float4(hi[4],hi[5],hi[6],hi[7]);
  }
}

// ---------------- Ws GEMM (enc layout A) -> bf16 + bias. grid (256,4), K=512 ----------------
__global__ void __launch_bounds__(256) k_ws128(const float* __restrict__ enc,
                                               const float* __restrict__ Ww,
                                               const float* __restrict__ Wb,
                                               __nv_bfloat16* __restrict__ Wsh){
  __shared__ __align__(16) float At[2][KT][132];
  __shared__ __align__(16) u64  WtU[2][KT][130];
  int b = blockIdx.x;              // batch index; m-tile = 128 l's of one b
  int n0 = blockIdx.y*128;
  int tid = threadIdx.x;
  int tm = tid & 15, tn = tid >> 4;
  int akk = tid >> 5, al4 = (tid & 31)*4;   // A: 8 kk x 128 l
  int wnn = tid >> 1, wk4 = (tid & 1)*4;    // W: 128 n x 8 kk
  u64 acc[4][8] = {};
  float4 ra, rw;

  auto loadT = [&](int t){
    int kc = t*KT;
    ra = *(const float4*)&enc[(size_t)b*CC*NL + (size_t)(kc + akk)*NL + al4];
    rw = *(const float4*)&Ww[(size_t)(n0 + wnn)*CC + kc + wk4];
  };
  auto storeT = [&](int buf){
    *(float4*)&At[buf][akk][al4] = ra;
    WtU[buf][wk4+0][wnn]=PACK2(rw.x,rw.x); WtU[buf][wk4+1][wnn]=PACK2(rw.y,rw.y);
    WtU[buf][wk4+2][wnn]=PACK2(rw.z,rw.z); WtU[buf][wk4+3][wnn]=PACK2(rw.w,rw.w);
  };

  loadT(0); storeT(0); __syncthreads();
  for (int t=0;t<64;t++){
    int buf = t & 1;
    if (t+1 < 64) loadT(t+1);
    MZ_COMPUTE(buf)
    if (t+1 < 64) storeT((t+1)&1);
    __syncthreads();
  }
  float4 bi0 = *(const float4*)&Wb[n0 + tn*8];
  float4 bi1 = *(const float4*)&Wb[n0 + tn*8 + 4];
  float bias[8] = {bi0.x,bi0.y,bi0.z,bi0.w,bi1.x,bi1.y,bi1.z,bi1.w};
  #pragma unroll
  for (int p=0;p<4;p++){
    float lo[8], hi[8];
    #pragma unroll
    for (int n=0;n<8;n++){ float2 v = UNPK(acc[p][n]); lo[n]=v.x+bias[n]; hi[n]=v.y+bias[n]; }
    int mA = b*128 + tm*8 + p*2;
    __nv_bfloat16* cA = Wsh + (size_t)mA*HH + n0 + tn*8;
    __nv_bfloat16* cB = cA + HH;
    #pragma unroll
    for (int n=0;n<8;n+=2){
      *(__nv_bfloat162*)(cA+n) = __floats2bfloat162_rn(lo[n], lo[n+1]);
      *(__nv_bfloat162*)(cB+n) = __floats2bfloat162_rn(hi[n], hi[n+1]);
    }
  }
}

// ---------------- logits GEMM (N=64): 64x64 tile K-split (kept from R4) ----------------
__global__ void __launch_bounds__(256) k_g64(const float* __restrict__ A0, int wA0,
                                             const float* __restrict__ W0, int s0, int o0,
                                             float* __restrict__ C0, float* __restrict__ C1,
                                             int ldc){
  __shared__ __align__(16) float At[2][16][68];
  __shared__ __align__(16) float Wt[2][16][68];
  int z = blockIdx.z;
  int kbase = z*256;
  float* C = z ? C1 : C0;
  int m0 = blockIdx.x*64, n0 = blockIdx.y*64;
  int tid = threadIdx.x, tm = tid & 15, tn = tid >> 4;
  u64 acc[4][2] = {};
  float4 ra, rw;
  int mm = tid >> 2, k4 = (tid & 3)*4;

  auto loadT = [&](int t){
    int kc = kbase + t*16;
    ra = *(const float4*)&A0[(size_t)(m0+mm)*wA0 + kc + k4];
    rw = *(const float4*)&W0[(size_t)(n0+mm)*s0 + o0 + kc + k4];
  };
  auto storeT = [&](int buf){
    At[buf][k4+0][mm]=ra.x; At[buf][k4+1][mm]=ra.y; At[buf][k4+2][mm]=ra.z; At[buf][k4+3][mm]=ra.w;
    Wt[buf][k4+0][mm]=rw.x; Wt[buf][k4+1][mm]=rw.y; Wt[buf][k4+2][mm]=rw.z; Wt[buf][k4+3][mm]=rw.w;
  };

  loadT(0); storeT(0); __syncthreads();
  for (int t=0;t<16;t++){
    int buf = t & 1;
    if (t+1 < 16) loadT(t+1);
    #pragma unroll
    for (int kk=0;kk<16;kk++){
      float4 av = *(const float4*)&At[buf][kk][tm*4];
      ulonglong2 wv = *(const ulonglong2*)&Wt[buf][kk][tn*4];
      u64 a0=PACK2(av.x,av.x), a1=PACK2(av.y,av.y), a2=PACK2(av.z,av.z), a3=PACK2(av.w,av.w);
      FMA2(acc[0][0],a0,wv.x); FMA2(acc[0][1],a0,wv.y);
      FMA2(acc[1][0],a1,wv.x); FMA2(acc[1][1],a1,wv.y);
      FMA2(acc[2][0],a2,wv.x); FMA2(acc[2][1],a2,wv.y);
      FMA2(acc[3][0],a3,wv.x); FMA2(acc[3][1],a3,wv.y);
    }
    if (t+1 < 16) storeT((t+1)&1);
    __syncthreads();
  }
  #pragma unroll
  for (int mi=0;mi<4;mi++){
    int m = m0 + tm*4 + mi;
    #pragma unroll
    for (int h=0;h<2;h++){
      float2 p = UNPK(acc[mi][h]);
      int n = n0 + tn*4 + h*2;
      *(float2*)&C[(size_t)m*ldc + n] = make_float2(p.x, p.y);
    }
  }
}

// ---------------- GRU pointwise: combine 6 gate partials ----------------
__global__ void __launch_bounds__(256) k_pw(const float* __restrict__ P,
                                            const float* __restrict__ xgp,
                                            const float* __restrict__ hprev,
                                            const float* __restrict__ bih,
                                            const float* __restrict__ bhh,
                                            float* __restrict__ hnew){
  int idx = blockIdx.x*256 + threadIdx.x;
  int b = idx >> 9, j = idx & (HH-1);
  size_t r0 = (size_t)b*(3*HH);
  const size_t PS = (size_t)BB*3*HH;
  float gr = bih[j] + bhh[j];
  float gz = bih[HH+j] + bhh[HH+j];
  float gi = bih[2*HH+j];
  float gh = bhh[2*HH+j];
  #pragma unroll
  for (int z=0; z<3; z++){
    const float* p = P + (size_t)z*PS + r0;
    gr += p[j]; gz += p[HH+j]; gi += p[2*HH+j];
  }
  #pragma unroll
  for (int z=3; z<6; z++){
    const float* p = P + (size_t)z*PS + r0;
    gr += p[j]; gz += p[HH+j]; gh += p[2*HH+j];
  }
  if (xgp){
    const float* x = xgp + r0;
    gr += x[j]; gz += x[HH+j]; gi += x[2*HH+j];
  }
  float r = 1.f/(1.f+expf(-gr));
  float z = 1.f/(1.f+expf(-gz));
  float n = tanhf(gi + r*gh);
  hnew[idx] = (1.f-z)*n + z*hprev[idx];
}

// ---------------- fc pointwise: sum 16 partials + relu ----------------
__global__ void __launch_bounds__(256) k_pwfc(const float* __restrict__ F,
                                              const float* __restrict__ fcb,
                                              float* __restrict__ y){
  int idx = blockIdx.x*256 + threadIdx.x;
  int j = idx & (HH-1);
  float v = fcb[j];
  #pragma unroll
  for (int z=0; z<16; z++) v += F[(size_t)z*BH + idx];
  y[idx] = fmaxf(v, 0.f);
}

// ---------------- attention (bf16 streams); Uh from 16 partials ----------------
__global__ void __launch_bounds__(256) k_attn(const __nv_bfloat16* __restrict__ Wsh,
                                              const __nv_bfloat16* __restrict__ ench,
                                              const float* __restrict__ Up,
                                              const float* __restrict__ aUb,
                                              const float* __restrict__ vw,
                                              const float* __restrict__ vb,
                                              float* __restrict__ ctx){
  __shared__ __align__(16) float us[HH];
  __shared__ __align__(16) float vs[HH];
  __shared__ __align__(16) float sc[NL];
  int b = blockIdx.x, tid = threadIdx.x;

  {
    float2 u = *(const float2*)&aUb[tid*2];
    #pragma unroll
    for (int z=0; z<16; z++){
      float2 p = *(const float2*)&Up[(size_t)z*BH + (size_t)b*HH + tid*2];
      u.x += p.x; u.y += p.y;
    }
    *(float2*)&us[tid*2] = u;
    *(float2*)&vs[tid*2] = *(const float2*)&vw[tid*2];
  }
  __syncthreads();

  {
    int l = tid >> 1, half = tid & 1;
    const uint4* wp = (const uint4*)(Wsh + ((size_t)(b*NL + l))*HH + half*256);
    float s = 0.f;
    #pragma unroll 4
    for (int i=0;i<32;i++){
      uint4 q = wp[i];
      const __nv_bfloat162* h2 = (const __nv_bfloat162*)&q;
      int off = half*256 + i*8;
      float4 u0 = *(const float4*)&us[off];
      float4 u1 = *(const float4*)&us[off+4];
      float4 v0 = *(const float4*)&vs[off];
      float4 v1 = *(const float4*)&vs[off+4];
      float2 w0=__bfloat1622float2(h2[0]), w1=__bfloat1622float2(h2[1]);
      float2 w2=__bfloat1622float2(h2[2]), w3=__bfloat1622float2(h2[3]);
      s += fmaxf(w0.x+u0.x,0.f)*v0.x + fmaxf(w0.y+u0.y,0.f)*v0.y
         + fmaxf(w1.x+u0.z,0.f)*v0.z + fmaxf(w1.y+u0.w,0.f)*v0.w
         + fmaxf(w2.x+u1.x,0.f)*v1.x + fmaxf(w2.y+u1.y,0.f)*v1.y
         + fmaxf(w3.x+u1.z,0.f)*v1.z + fmaxf(w3.y+u1.w,0.f)*v1.w;
    }
    s += __shfl_xor_sync(0xffffffffu, s, 1);
    if (!half) sc[l] = s + vb[0];
  }
  __syncthreads();
  if (tid < 32){
    float m = -1e30f;
    for (int l = tid; l < NL; l += 32) m = fmaxf(m, sc[l]);
    #pragma unroll
    for (int o=16;o;o>>=1) m = fmaxf(m, __shfl_xor_sync(0xffffffffu,m,o));
    float s = 0.f;
    for (int l = tid; l < NL; l += 32){ float e = expf(sc[l]-m); sc[l] = e; s += e; }
    #pragma unroll
    for (int o=16;o;o>>=1) s += __shfl_xor_sync(0xffffffffu,s,o);
    float inv = 1.f/s;
    for (int l = tid; l < NL; l += 32) sc[l] *= inv;
  }
  __syncthreads();
  #pragma unroll
  for (int cc=0;cc<2;cc++){
    int c = tid + cc*256;
    const uint4* ep = (const uint4*)(ench + ((size_t)b*CC + c)*NL);
    float s = 0.f;
    #pragma unroll 4
    for (int i=0;i<16;i++){
      uint4 q = ep[i];
      const __nv_bfloat162* h2 = (const __nv_bfloat162*)&q;
      float4 a0 = *(const float4*)&sc[i*8];
      float4 a1 = *(const float4*)&sc[i*8+4];
      float2 e0=__bfloat1622float2(h2[0]), e1=__bfloat1622float2(h2[1]);
      float2 e2=__bfloat1622float2(h2[2]), e3=__bfloat1622float2(h2[3]);
      s += e0.x*a0.x + e0.y*a0.y + e1.x*a0.z + e1.y*a0.w
         + e2.x*a1.x + e2.y*a1.y + e3.x*a1.z + e3.y*a1.w;
    }
    ctx[(size_t)b*CC + c] = s;
  }
}

// ---------------- per-token NLL from logits partials ----------------
__global__ void __launch_bounds__(256) k_nll(const float* __restrict__ LA,
                                             const float* __restrict__ LB,
                                             const float* __restrict__ clsb,
                                             const int* __restrict__ seq,
                                             float* __restrict__ nll,
                                             float* __restrict__ msk){
  int idx = blockIdx.x*256 + threadIdx.x;
  int t = idx >> 8, b = idx & 255;
  float lg[VV];
  const float4* pa = (const float4*)(LA + (size_t)idx*VV);
  const float4* pb = (const float4*)(LB + (size_t)idx*VV);
  float m = -1e30f;
  #pragma unroll
  for (int i=0;i<16;i++){
    float4 a = pa[i], c = pb[i];
    float4 d = *(const float4*)&clsb[i*4];
    lg[i*4+0] = a.x + c.x + d.x;
    lg[i*4+1] = a.y + c.y + d.y;
    lg[i*4+2] = a.z + c.z + d.z;
    lg[i*4+3] = a.w + c.w + d.w;
  }
  #pragma unroll
  for (int v=0;v<VV;v++) m = fmaxf(m, lg[v]);
  float se = 0.f;
  #pragma unroll
  for (int v=0;v<VV;v++) se += expf(lg[v]-m);
  int label = seq[b*LSEQ + t + 1];
  float lp = lg[label] - m - logf(se);
  bool mk = label > 0;
  nll[idx] = mk ? -lp : 0.f;
  msk[idx] = mk ? 1.f : 0.f;
}

// ---------------- deterministic final reduction ----------------
__global__ void __launch_bounds__(256) k_reduce(const float* __restrict__ nll,
                                                const float* __restrict__ msk,
                                                float* __restrict__ out){
  __shared__ float sn[256], sm[256];
  int tid = threadIdx.x;
  float a = 0.f, c = 0.f;
  for (int i = tid; i < NTOK; i += 256){ a += nll[i]; c += msk[i]; }
  sn[tid] = a; sm[tid] = c;
  __syncthreads();
  for (int o = 128; o; o >>= 1){
    if (tid < o){ sn[tid] += sn[tid+o]; sm[tid] += sm[tid+o]; }
    __syncthreads();
  }
  if (tid == 0) out[0] = sn[0] / sm[0];
}

// ---------------- host orchestration ----------------
extern "C" void kernel_launch(void* const* d_in, const int* in_sizes, int n_in,
                              void* d_out, int out_size){
  (void)in_sizes; (void)n_in; (void)out_size;
  const float* enc   = (const float*)d_in[0];
  const int*   seq   = (const int*)  d_in[1];
  const float* emb   = (const float*)d_in[3];
  const float* inis  = (const float*)d_in[4];
  const float* aWw   = (const float*)d_in[5];
  const float* aWb   = (const float*)d_in[6];
  const float* aUw   = (const float*)d_in[7];
  const float* aUb   = (const float*)d_in[8];
  const float* avw   = (const float*)d_in[9];
  const float* avb   = (const float*)d_in[10];
  const float* fcw   = (const float*)d_in[11];
  const float* fcb   = (const float*)d_in[12];
  const float* clsw  = (const float*)d_in[13];
  const float* clsb  = (const float*)d_in[14];
  const float* g0wih = (const float*)d_in[15];
  const float* g0whh = (const float*)d_in[16];
  const float* g0bih = (const float*)d_in[17];
  const float* g0bhh = (const float*)d_in[18];
  const float* g1wih = (const float*)d_in[19];
  const float* g1whh = (const float*)d_in[20];
  const float* g1bih = (const float*)d_in[21];
  const float* g1bhh = (const float*)d_in[22];

  __nv_bfloat16 *Wsh, *ench;
  float *xg, *xs, *ys, *y0, *h0b, *h1b, *gp, *fp, *Up, *ctx, *lg, *nll, *msk;
  cudaGetSymbolAddress((void**)&Wsh,  g_Wsh);
  cudaGetSymbolAddress((void**)&ench, g_ench);
  cudaGetSymbolAddress((void**)&xg,   g_xg);
  cudaGetSymbolAddress((void**)&xs,   g_xs);
  cudaGetSymbolAddress((void**)&ys,   g_ys);
  cudaGetSymbolAddress((void**)&y0,   g_y0);
  cudaGetSymbolAddress((void**)&h0b,  g_h0buf);
  cudaGetSymbolAddress((void**)&h1b,  g_h1buf);
  cudaGetSymbolAddress((void**)&gp,   g_gp);
  cudaGetSymbolAddress((void**)&fp,   g_fp);
  cudaGetSymbolAddress((void**)&Up,   g_Up);
  cudaGetSymbolAddress((void**)&ctx,  g_ctx);
  cudaGetSymbolAddress((void**)&lg,   g_lg);
  cudaGetSymbolAddress((void**)&nll,  g_nll);
  cudaGetSymbolAddress((void**)&msk,  g_msk);

  float* LG[2] = {lg, lg+(size_t)NTOK*VV};

  // one-time precompute
  k_inith<<<(BH+255)/256, 256>>>(inis, h0b, h1b);
  k_embed<<<(TT*BH+255)/256, 256>>>(emb, seq, xs);
  k_tobf16<<<(BB*CC*NL/4+255)/256, 256>>>(enc, ench, BB*CC*NL/4);
  k_ws128<<<dim3(BB, 4), 256>>>(enc, aWw, aWb, Wsh);
  // xg[t*B+b, 3H] = x_t @ wih[:, 512:1024]^T  (M=5888, N=1536, full K)
  k_mz<<<dim3(46, 12, 1), 256>>>(xs, 512, g0wih, 1024, 512,
                                 nullptr, 0, nullptr, 0, 0,
                                 1, 512, 512, xg, 3*HH);

  auto attn_fc = [&](const float* h1cur, float* yout){
    // Uh partials: 16 K-slices of 32
    k_mz<<<dim3(2, 4, 16), 256>>>(h1cur, HH, aUw, 512, 0,
                                  nullptr, 0, nullptr, 0, 0,
                                  16, 32, 512, Up, HH);
    k_attn<<<BB, 256>>>(Wsh, ench, Up, aUb, avw, avb, ctx);
    // fc partials: set0 ctx vs fcw[:, :512], set1 h vs fcw[:, 512:], 8 slices of 64 each
    k_mz<<<dim3(2, 4, 16), 256>>>(ctx, CC, fcw, 1024, 0,
                                  h1cur, HH, fcw, 1024, 512,
                                  8, 64, 512, fp, HH);
    k_pwfc<<<BH/256, 256>>>(fp, fcb, yout);
  };

  // y0
  attn_fc(h1b, y0);

  const float* yprev = y0;
  for (int t = 0; t < TT; t++){
    float* h0r = h0b + (size_t)(t & 1)*BH;
    float* h0w = h0b + (size_t)((t+1) & 1)*BH;
    float* h1r = h1b + (size_t)(t & 1)*BH;
    float* h1w = h1b + (size_t)((t+1) & 1)*BH;
    // GRU0: set0 y_prev @ wih[:, :512], set1 h0prev @ whh; 3 K-slices/set {176,176,160}
    k_mz<<<dim3(2, 12, 6), 256>>>(yprev, HH, g0wih, 1024, 0,
                                  h0r, HH, g0whh, 512, 0,
                                  3, 176, 512, gp, 3*HH);
    k_pw<<<BH/256, 256>>>(gp, xg + (size_t)t*BB*3*HH, h0r, g0bih, g0bhh, h0w);
    // GRU1
    k_mz<<<dim3(2, 12, 6), 256>>>(h0w, HH, g1wih, 512, 0,
                                  h1r, HH, g1whh, 512, 0,
                                  3, 176, 512, gp, 3*HH);
    k_pw<<<BH/256, 256>>>(gp, (const float*)nullptr, h1r, g1bih, g1bhh, h1w);
    // attention + out_proj
    attn_fc(h1w, ys + (size_t)t*BH);
    yprev = ys + (size_t)t*BH;
  }

  // logits (M=5888, N=64, K=512 in 2 halves) + NLL + reduce
  k_g64<<<dim3(92, 1, 2), 256>>>(ys, HH, clsw, 512, 0, LG[0], LG[1], VV);
  k_nll<<<NTOK/256, 256>>>(LG[0], LG[1], clsb, seq, nll, msk);
  k_reduce<<<1, 256>>>(nll, msk, (float*)d_out);
}

// round 6
// speedup vs baseline: 2.0885x; 2.0885x over previous
#include <cuda_runtime.h>
#include <cuda_bf16.h>
#include <math.h>

#define BB 256
#define HH 512
#define CC 512
#define NL 128
#define TT 23
#define LSEQ 24
#define VV 64
#define BH (BB*HH)
#define NTOK (TT*BB)
#define KC 32          // k-chunk per smem stage
#define ASTR 40        // smem row stride in bf16 elems (80B: 8/16B aligned, bank-shift 20)

typedef unsigned long long u64;
typedef unsigned int u32;

__device__ __forceinline__ void MMA16816(float &d0, float &d1, float &d2, float &d3,
                                         u32 a0, u32 a1, u32 a2, u32 a3,
                                         u32 b0, u32 b1){
  asm volatile("mma.sync.aligned.m16n8k16.row.col.f32.bf16.bf16.f32 "
               "{%0,%1,%2,%3},{%4,%5,%6,%7},{%8,%9},{%0,%1,%2,%3};"
               : "+f"(d0), "+f"(d1), "+f"(d2), "+f"(d3)
               : "r"(a0), "r"(a1), "r"(a2), "r"(a3), "r"(b0), "r"(b1));
}
__device__ __forceinline__ u32 BF2U(__nv_bfloat162 v){ return *reinterpret_cast<u32*>(&v); }
__device__ __forceinline__ void FMA2(u64 &d, u64 a, u64 b){
  asm("fma.rn.f32x2 %0, %1, %2, %0;" : "+l"(d) : "l"(a), "l"(b));
}
__device__ __forceinline__ u64 PACK2(float x, float y){
  u64 r; asm("mov.b64 %0, {%1, %2};" : "=l"(r) : "f"(x), "f"(y)); return r;
}
__device__ __forceinline__ float2 UNPK(u64 v){
  float2 r; asm("mov.b64 {%0, %1}, %2;" : "=f"(r.x), "=f"(r.y) : "l"(v)); return r;
}

// ---------------- static scratch ----------------
__device__ __nv_bfloat16 g_Wsh[(size_t)BB*NL*HH];
__device__ __nv_bfloat16 g_ench[(size_t)BB*CC*NL];
__device__ __nv_bfloat16 g_w_aWw[HH*CC];
__device__ __nv_bfloat16 g_w_aUw[HH*HH];
__device__ __nv_bfloat16 g_w_fcw[HH*(CC+HH)];
__device__ __nv_bfloat16 g_w_g0wih[3*HH*2*HH];
__device__ __nv_bfloat16 g_w_g0whh[3*HH*HH];
__device__ __nv_bfloat16 g_w_g1wih[3*HH*HH];
__device__ __nv_bfloat16 g_w_g1whh[3*HH*HH];
__device__ float g_xg[(size_t)TT*BB*3*HH];
__device__ float g_xs[(size_t)TT*BH];
__device__ float g_ys[(size_t)TT*BH];
__device__ float g_y0[BH];
__device__ float g_h0buf[2][BH];
__device__ float g_h1buf[2][BH];
__device__ float g_gp[4][(size_t)BB*3*HH];
__device__ float g_fp[4][BH];
__device__ float g_Up[2][BH];
__device__ float g_ctx[BH];
__device__ float g_lg[2][(size_t)NTOK*VV];
__device__ float g_nll[NTOK];
__device__ float g_msk[NTOK];

// ---------------- init hidden states ----------------
__global__ void k_inith(const float* __restrict__ init_state,
                        float* __restrict__ h0, float* __restrict__ h1){
  int idx = blockIdx.x*blockDim.x + threadIdx.x;
  if (idx < BH){
    int j = idx & (HH-1);
    h0[idx] = init_state[j];
    h1[idx] = init_state[HH + j];
  }
}

// ---------------- embedding gather ----------------
__global__ void k_embed(const float* __restrict__ emb, const int* __restrict__ seq,
                        float* __restrict__ xs){
  int idx = blockIdx.x*blockDim.x + threadIdx.x;
  if (idx < TT*BH){
    int h = idx & (HH-1);
    int r = idx >> 9;
    int b = r & (BB-1);
    int t = r >> 8;
    int tok = seq[b*LSEQ + t];
    xs[idx] = emb[(size_t)tok*HH + h];
  }
}

// ---------------- fp32 -> bf16 copy ----------------
__global__ void k_tobf16(const float* __restrict__ in, __nv_bfloat16* __restrict__ out, int n4){
  int idx = blockIdx.x*blockDim.x + threadIdx.x;
  if (idx < n4){
    float4 v = *(const float4*)&in[(size_t)idx*4];
    *(__nv_bfloat162*)&out[(size_t)idx*4]   = __floats2bfloat162_rn(v.x, v.y);
    *(__nv_bfloat162*)&out[(size_t)idx*4+2] = __floats2bfloat162_rn(v.z, v.w);
  }
}

// ============ bf16 mma GEMM core (64x128 block tile, 8 warps of 32x32) ============
// Computes C[m,n] += sum_k A[m,k]*W[n,k].  A fp32 in gmem (converted while staging),
// W bf16 in gmem.  Frag layout per mma.m16n8k16 row.col.
#define MMA_FRAGS_AND_COMPUTE(buf)                                             \
  _Pragma("unroll")                                                            \
  for (int k16 = 0; k16 < KC; k16 += 16){                                      \
    u32 af[2][4]; u32 bf[4][2];                                                \
    _Pragma("unroll")                                                          \
    for (int mt = 0; mt < 2; mt++){                                            \
      int r = wm + mt*16 + gid;                                                \
      af[mt][0] = *(const u32*)&At[buf][r*ASTR      + k16 + tig*2];            \
      af[mt][1] = *(const u32*)&At[buf][(r+8)*ASTR  + k16 + tig*2];            \
      af[mt][2] = *(const u32*)&At[buf][r*ASTR      + k16 + tig*2 + 8];        \
      af[mt][3] = *(const u32*)&At[buf][(r+8)*ASTR  + k16 + tig*2 + 8];        \
    }                                                                          \
    _Pragma("unroll")                                                          \
    for (int nt = 0; nt < 4; nt++){                                            \
      int r = wn + nt*8 + gid;                                                 \
      bf[nt][0] = *(const u32*)&Wt[buf][r*ASTR + k16 + tig*2];                 \
      bf[nt][1] = *(const u32*)&Wt[buf][r*ASTR + k16 + tig*2 + 8];             \
    }                                                                          \
    _Pragma("unroll")                                                          \
    for (int mt = 0; mt < 2; mt++)                                             \
      _Pragma("unroll")                                                        \
      for (int nt = 0; nt < 4; nt++)                                           \
        MMA16816(acc[mt][nt][0], acc[mt][nt][1], acc[mt][nt][2], acc[mt][nt][3],\
                 af[mt][0], af[mt][1], af[mt][2], af[mt][3],                   \
                 bf[nt][0], bf[nt][1]);                                        \
  }

// generic: 2 operand sets, K-sliced; raw fp32 partial to Cb + z*M*ldc
__global__ void __launch_bounds__(256) k_mmT(
    const float* __restrict__ A0, int wA0,
    const __nv_bfloat16* __restrict__ W0, int s0, int o0,
    const float* __restrict__ A1, int wA1,
    const __nv_bfloat16* __restrict__ W1, int s1, int o1,
    int zPerSet, int kSlice, float* __restrict__ Cb, int ldc){
  __shared__ __align__(16) __nv_bfloat16 At[2][64*ASTR];
  __shared__ __align__(16) __nv_bfloat16 Wt[2][128*ASTR];
  int z = blockIdx.z;
  int set = z / zPerSet;
  int kb = (z - set*zPerSet) * kSlice;
  const float* A = set ? A1 : A0;
  const __nv_bfloat16* W = set ? W1 : W0;
  int wA = set ? wA1 : wA0;
  int s  = set ? s1 : s0;
  int o  = set ? o1 : o0;
  int M = gridDim.x * 64;
  float* C = Cb + (size_t)z * M * ldc;

  int m0 = blockIdx.x*64, n0 = blockIdx.y*128;
  int tid = threadIdx.x;
  int warp = tid >> 5, lane = tid & 31;
  int wm = (warp & 1)*32, wn = (warp >> 1)*32;
  int gid = lane >> 2, tig = lane & 3;
  float acc[2][4][4] = {};

  float4 ra[2]; uint4 rw[2];
  auto loadT = [&](int t){
    int kc = kb + t*KC;
    #pragma unroll
    for (int i=0;i<2;i++){
      int idx = tid + i*256;
      int r = idx >> 3, k4 = (idx & 7)*4;
      ra[i] = *(const float4*)&A[(size_t)(m0+r)*wA + kc + k4];
      int rr = idx >> 2, k8 = (idx & 3)*8;
      rw[i] = *(const uint4*)&W[(size_t)(n0+rr)*s + o + kc + k8];
    }
  };
  auto storeT = [&](int buf){
    #pragma unroll
    for (int i=0;i<2;i++){
      int idx = tid + i*256;
      int r = idx >> 3, k4 = (idx & 7)*4;
      u32 p0 = BF2U(__floats2bfloat162_rn(ra[i].x, ra[i].y));
      u32 p1 = BF2U(__floats2bfloat162_rn(ra[i].z, ra[i].w));
      *(uint2*)&At[buf][r*ASTR + k4] = make_uint2(p0, p1);
      int rr = idx >> 2, k8 = (idx & 3)*8;
      *(uint4*)&Wt[buf][rr*ASTR + k8] = rw[i];
    }
  };

  int ntc = kSlice / KC;
  loadT(0); storeT(0); __syncthreads();
  for (int t=0;t<ntc;t++){
    int buf = t & 1;
    if (t+1 < ntc) loadT(t+1);
    MMA_FRAGS_AND_COMPUTE(buf)
    if (t+1 < ntc) storeT((t+1)&1);
    __syncthreads();
  }

  #pragma unroll
  for (int mt=0;mt<2;mt++){
    #pragma unroll
    for (int nt=0;nt<4;nt++){
      int m = m0 + wm + mt*16 + gid;
      int n = n0 + wn + nt*8 + tig*2;
      *(float2*)&C[(size_t)m*ldc + n]     = make_float2(acc[mt][nt][0], acc[mt][nt][1]);
      *(float2*)&C[(size_t)(m+8)*ldc + n] = make_float2(acc[mt][nt][2], acc[mt][nt][3]);
    }
  }
}

// Ws GEMM: A from enc (k-major layout), bias add, bf16 output
__global__ void __launch_bounds__(256) k_wsT(
    const float* __restrict__ enc,
    const __nv_bfloat16* __restrict__ Wwb,
    const float* __restrict__ Wb,
    __nv_bfloat16* __restrict__ Wsh){
  __shared__ __align__(16) __nv_bfloat16 At[2][64*ASTR];
  __shared__ __align__(16) __nv_bfloat16 Wt[2][128*ASTR];
  int m0 = blockIdx.x*64;
  int b = m0 >> 7, l0 = m0 & 127;
  int n0 = blockIdx.y*128;
  int tid = threadIdx.x;
  int warp = tid >> 5, lane = tid & 31;
  int wm = (warp & 1)*32, wn = (warp >> 1)*32;
  int gid = lane >> 2, tig = lane & 3;
  float acc[2][4][4] = {};

  float4 ra[2]; uint4 rw[2];
  auto loadT = [&](int t){
    int kc = t*KC;
    #pragma unroll
    for (int i=0;i<2;i++){
      int idx = tid + i*256;
      int k = idx >> 4, l4 = (idx & 15)*4;
      ra[i] = *(const float4*)&enc[(size_t)b*CC*NL + (size_t)(kc+k)*NL + l0 + l4];
      int rr = idx >> 2, k8 = (idx & 3)*8;
      rw[i] = *(const uint4*)&Wwb[(size_t)(n0+rr)*CC + kc + k8];
    }
  };
  auto storeT = [&](int buf){
    #pragma unroll
    for (int i=0;i<2;i++){
      int idx = tid + i*256;
      int k = idx >> 4, l4 = (idx & 15)*4;
      At[buf][(l4+0)*ASTR + k] = __float2bfloat16(ra[i].x);
      At[buf][(l4+1)*ASTR + k] = __float2bfloat16(ra[i].y);
      At[buf][(l4+2)*ASTR + k] = __float2bfloat16(ra[i].z);
      At[buf][(l4+3)*ASTR + k] = __float2bfloat16(ra[i].w);
      int rr = idx >> 2, k8 = (idx & 3)*8;
      *(uint4*)&Wt[buf][rr*ASTR + k8] = rw[i];
    }
  };

  loadT(0); storeT(0); __syncthreads();
  for (int t=0;t<16;t++){
    int buf = t & 1;
    if (t+1 < 16) loadT(t+1);
    MMA_FRAGS_AND_COMPUTE(buf)
    if (t+1 < 16) storeT((t+1)&1);
    __syncthreads();
  }

  #pragma unroll
  for (int mt=0;mt<2;mt++){
    #pragma unroll
    for (int nt=0;nt<4;nt++){
      int m = m0 + wm + mt*16 + gid;
      int n = n0 + wn + nt*8 + tig*2;
      float2 bi = *(const float2*)&Wb[n];
      *(__nv_bfloat162*)&Wsh[(size_t)m*HH + n] =
          __floats2bfloat162_rn(acc[mt][nt][0]+bi.x, acc[mt][nt][1]+bi.y);
      *(__nv_bfloat162*)&Wsh[(size_t)(m+8)*HH + n] =
          __floats2bfloat162_rn(acc[mt][nt][2]+bi.x, acc[mt][nt][3]+bi.y);
    }
  }
}

// ---------------- logits GEMM (fp32, N=64, K-split 2) ----------------
__global__ void __launch_bounds__(256) k_g64(const float* __restrict__ A0, int wA0,
                                             const float* __restrict__ W0, int s0, int o0,
                                             float* __restrict__ C0, float* __restrict__ C1,
                                             int ldc){
  __shared__ __align__(16) float At[2][16][68];
  __shared__ __align__(16) float Wt[2][16][68];
  int z = blockIdx.z;
  int kbase = z*256;
  float* C = z ? C1 : C0;
  int m0 = blockIdx.x*64, n0 = blockIdx.y*64;
  int tid = threadIdx.x, tm = tid & 15, tn = tid >> 4;
  u64 acc[4][2] = {};
  float4 ra, rw;
  int mm = tid >> 2, k4 = (tid & 3)*4;

  auto loadT = [&](int t){
    int kc = kbase + t*16;
    ra = *(const float4*)&A0[(size_t)(m0+mm)*wA0 + kc + k4];
    rw = *(const float4*)&W0[(size_t)(n0+mm)*s0 + o0 + kc + k4];
  };
  auto storeT = [&](int buf){
    At[buf][k4+0][mm]=ra.x; At[buf][k4+1][mm]=ra.y; At[buf][k4+2][mm]=ra.z; At[buf][k4+3][mm]=ra.w;
    Wt[buf][k4+0][mm]=rw.x; Wt[buf][k4+1][mm]=rw.y; Wt[buf][k4+2][mm]=rw.z; Wt[buf][k4+3][mm]=rw.w;
  };

  loadT(0); storeT(0); __syncthreads();
  for (int t=0;t<16;t++){
    int buf = t & 1;
    if (t+1 < 16) loadT(t+1);
    #pragma unroll
    for (int kk=0;kk<16;kk++){
      float4 av = *(const float4*)&At[buf][kk][tm*4];
      ulonglong2 wv = *(const ulonglong2*)&Wt[buf][kk][tn*4];
      u64 a0=PACK2(av.x,av.x), a1=PACK2(av.y,av.y), a2=PACK2(av.z,av.z), a3=PACK2(av.w,av.w);
      FMA2(acc[0][0],a0,wv.x); FMA2(acc[0][1],a0,wv.y);
      FMA2(acc[1][0],a1,wv.x); FMA2(acc[1][1],a1,wv.y);
      FMA2(acc[2][0],a2,wv.x); FMA2(acc[2][1],a2,wv.y);
      FMA2(acc[3][0],a3,wv.x); FMA2(acc[3][1],a3,wv.y);
    }
    if (t+1 < 16) storeT((t+1)&1);
    __syncthreads();
  }
  #pragma unroll
  for (int mi=0;mi<4;mi++){
    int m = m0 + tm*4 + mi;
    #pragma unroll
    for (int h=0;h<2;h++){
      float2 p = UNPK(acc[mi][h]);
      int n = n0 + tn*4 + h*2;
      *(float2*)&C[(size_t)m*ldc + n] = make_float2(p.x, p.y);
    }
  }
}

// ---------------- GRU pointwise: combine 4 gate partials ----------------
__global__ void __launch_bounds__(256) k_pw(const float* __restrict__ P0,
                                            const float* __restrict__ P1,
                                            const float* __restrict__ P2,
                                            const float* __restrict__ P3,
                                            const float* __restrict__ xg,
                                            const float* __restrict__ hprev,
                                            const float* __restrict__ bih,
                                            const float* __restrict__ bhh,
                                            float* __restrict__ hnew){
  int idx = blockIdx.x*256 + threadIdx.x;
  int b = idx >> 9, j = idx & (HH-1);
  size_t r0 = (size_t)b*(3*HH);
  float gr = P0[r0+j] + P1[r0+j] + P2[r0+j] + P3[r0+j] + bih[j] + bhh[j];
  float gz = P0[r0+HH+j] + P1[r0+HH+j] + P2[r0+HH+j] + P3[r0+HH+j] + bih[HH+j] + bhh[HH+j];
  float gi = P0[r0+2*HH+j] + P1[r0+2*HH+j] + bih[2*HH+j];
  float gh = P2[r0+2*HH+j] + P3[r0+2*HH+j] + bhh[2*HH+j];
  if (xg){
    gr += xg[r0+j]; gz += xg[r0+HH+j]; gi += xg[r0+2*HH+j];
  }
  float r = 1.f/(1.f+expf(-gr));
  float z = 1.f/(1.f+expf(-gz));
  float n = tanhf(gi + r*gh);
  hnew[idx] = (1.f-z)*n + z*hprev[idx];
}

// ---------------- fc pointwise ----------------
__global__ void __launch_bounds__(256) k_pwfc(const float* __restrict__ F0,
                                              const float* __restrict__ F1,
                                              const float* __restrict__ F2,
                                              const float* __restrict__ F3,
                                              const float* __restrict__ fcb,
                                              float* __restrict__ y){
  int idx = blockIdx.x*256 + threadIdx.x;
  int j = idx & (HH-1);
  float v = F0[idx] + F1[idx] + F2[idx] + F3[idx] + fcb[j];
  y[idx] = fmaxf(v, 0.f);
}

// ---------------- attention ----------------
__global__ void __launch_bounds__(256) k_attn(const __nv_bfloat16* __restrict__ Wsh,
                                              const __nv_bfloat16* __restrict__ ench,
                                              const float* __restrict__ UhA,
                                              const float* __restrict__ UhB,
                                              const float* __restrict__ aUb,
                                              const float* __restrict__ vw,
                                              const float* __restrict__ vb,
                                              float* __restrict__ ctx){
  __shared__ __align__(16) float us[HH];
  __shared__ __align__(16) float vs[HH];
  __shared__ __align__(16) float sc[NL];
  int b = blockIdx.x, tid = threadIdx.x;

  {
    float2 a = *(const float2*)&UhA[(size_t)b*HH + tid*2];
    float2 c = *(const float2*)&UhB[(size_t)b*HH + tid*2];
    float2 u = *(const float2*)&aUb[tid*2];
    us[tid*2]   = a.x + c.x + u.x;
    us[tid*2+1] = a.y + c.y + u.y;
    *(float2*)&vs[tid*2] = *(const float2*)&vw[tid*2];
  }
  __syncthreads();

  {
    int l = tid >> 1, half = tid & 1;
    const uint4* wp = (const uint4*)(Wsh + ((size_t)(b*NL + l))*HH + half*256);
    float s = 0.f;
    #pragma unroll 4
    for (int i=0;i<32;i++){
      uint4 q = wp[i];
      const __nv_bfloat162* h2 = (const __nv_bfloat162*)&q;
      int off = half*256 + i*8;
      float4 u0 = *(const float4*)&us[off];
      float4 u1 = *(const float4*)&us[off+4];
      float4 v0 = *(const float4*)&vs[off];
      float4 v1 = *(const float4*)&vs[off+4];
      float2 w0=__bfloat1622float2(h2[0]), w1=__bfloat1622float2(h2[1]);
      float2 w2=__bfloat1622float2(h2[2]), w3=__bfloat1622float2(h2[3]);
      s += fmaxf(w0.x+u0.x,0.f)*v0.x + fmaxf(w0.y+u0.y,0.f)*v0.y
         + fmaxf(w1.x+u0.z,0.f)*v0.z + fmaxf(w1.y+u0.w,0.f)*v0.w
         + fmaxf(w2.x+u1.x,0.f)*v1.x + fmaxf(w2.y+u1.y,0.f)*v1.y
         + fmaxf(w3.x+u1.z,0.f)*v1.z + fmaxf(w3.y+u1.w,0.f)*v1.w;
    }
    s += __shfl_xor_sync(0xffffffffu, s, 1);
    if (!half) sc[l] = s + vb[0];
  }
  __syncthreads();
  if (tid < 32){
    float m = -1e30f;
    for (int l = tid; l < NL; l += 32) m = fmaxf(m, sc[l]);
    #pragma unroll
    for (int o=16;o;o>>=1) m = fmaxf(m, __shfl_xor_sync(0xffffffffu,m,o));
    float s = 0.f;
    for (int l = tid; l < NL; l += 32){ float e = expf(sc[l]-m); sc[l] = e; s += e; }
    #pragma unroll
    for (int o=16;o;o>>=1) s += __shfl_xor_sync(0xffffffffu,s,o);
    float inv = 1.f/s;
    for (int l = tid; l < NL; l += 32) sc[l] *= inv;
  }
  __syncthreads();
  #pragma unroll
  for (int cc=0;cc<2;cc++){
    int c = tid + cc*256;
    const uint4* ep = (const uint4*)(ench + ((size_t)b*CC + c)*NL);
    float s = 0.f;
    #pragma unroll 4
    for (int i=0;i<16;i++){
      uint4 q = ep[i];
      const __nv_bfloat162* h2 = (const __nv_bfloat162*)&q;
      float4 a0 = *(const float4*)&sc[i*8];
      float4 a1 = *(const float4*)&sc[i*8+4];
      float2 e0=__bfloat1622float2(h2[0]), e1=__bfloat1622float2(h2[1]);
      float2 e2=__bfloat1622float2(h2[2]), e3=__bfloat1622float2(h2[3]);
      s += e0.x*a0.x + e0.y*a0.y + e1.x*a0.z + e1.y*a0.w
         + e2.x*a1.x + e2.y*a1.y + e3.x*a1.z + e3.y*a1.w;
    }
    ctx[(size_t)b*CC + c] = s;
  }
}

// ---------------- per-token NLL ----------------
__global__ void __launch_bounds__(256) k_nll(const float* __restrict__ LA,
                                             const float* __restrict__ LB,
                                             const float* __restrict__ clsb,
                                             const int* __restrict__ seq,
                                             float* __restrict__ nll,
                                             float* __restrict__ msk){
  int idx = blockIdx.x*256 + threadIdx.x;
  int t = idx >> 8, b = idx & 255;
  float lg[VV];
  const float4* pa = (const float4*)(LA + (size_t)idx*VV);
  const float4* pb = (const float4*)(LB + (size_t)idx*VV);
  float m = -1e30f;
  #pragma unroll
  for (int i=0;i<16;i++){
    float4 a = pa[i], c = pb[i];
    float4 d = *(const float4*)&clsb[i*4];
    lg[i*4+0] = a.x + c.x + d.x;
    lg[i*4+1] = a.y + c.y + d.y;
    lg[i*4+2] = a.z + c.z + d.z;
    lg[i*4+3] = a.w + c.w + d.w;
  }
  #pragma unroll
  for (int v=0;v<VV;v++) m = fmaxf(m, lg[v]);
  float se = 0.f;
  #pragma unroll
  for (int v=0;v<VV;v++) se += expf(lg[v]-m);
  int label = seq[b*LSEQ + t + 1];
  float lp = lg[label] - m - logf(se);
  bool mk = label > 0;
  nll[idx] = mk ? -lp : 0.f;
  msk[idx] = mk ? 1.f : 0.f;
}

// ---------------- deterministic final reduction ----------------
__global__ void __launch_bounds__(256) k_reduce(const float* __restrict__ nll,
                                                const float* __restrict__ msk,
                                                float* __restrict__ out){
  __shared__ float sn[256], sm[256];
  int tid = threadIdx.x;
  float a = 0.f, c = 0.f;
  for (int i = tid; i < NTOK; i += 256){ a += nll[i]; c += msk[i]; }
  sn[tid] = a; sm[tid] = c;
  __syncthreads();
  for (int o = 128; o; o >>= 1){
    if (tid < o){ sn[tid] += sn[tid+o]; sm[tid] += sm[tid+o]; }
    __syncthreads();
  }
  if (tid == 0) out[0] = sn[0] / sm[0];
}

// ---------------- host orchestration ----------------
extern "C" void kernel_launch(void* const* d_in, const int* in_sizes, int n_in,
                              void* d_out, int out_size){
  (void)in_sizes; (void)n_in; (void)out_size;
  const float* enc   = (const float*)d_in[0];
  const int*   seq   = (const int*)  d_in[1];
  const float* emb   = (const float*)d_in[3];
  const float* inis  = (const float*)d_in[4];
  const float* aWw   = (const float*)d_in[5];
  const float* aWb   = (const float*)d_in[6];
  const float* aUw   = (const float*)d_in[7];
  const float* aUb   = (const float*)d_in[8];
  const float* avw   = (const float*)d_in[9];
  const float* avb   = (const float*)d_in[10];
  const float* fcw   = (const float*)d_in[11];
  const float* fcb   = (const float*)d_in[12];
  const float* clsw  = (const float*)d_in[13];
  const float* clsb  = (const float*)d_in[14];
  const float* g0wih = (const float*)d_in[15];
  const float* g0whh = (const float*)d_in[16];
  const float* g0bih = (const float*)d_in[17];
  const float* g0bhh = (const float*)d_in[18];
  const float* g1wih = (const float*)d_in[19];
  const float* g1whh = (const float*)d_in[20];
  const float* g1bih = (const float*)d_in[21];
  const float* g1bhh = (const float*)d_in[22];

  __nv_bfloat16 *Wsh, *ench, *waWw, *waUw, *wfcw, *w0ih, *w0hh, *w1ih, *w1hh;
  float *xg, *xs, *ys, *y0, *h0b, *h1b, *gp, *fp, *Up, *ctx, *lg, *nll, *msk;
  cudaGetSymbolAddress((void**)&Wsh,  g_Wsh);
  cudaGetSymbolAddress((void**)&ench, g_ench);
  cudaGetSymbolAddress((void**)&waWw, g_w_aWw);
  cudaGetSymbolAddress((void**)&waUw, g_w_aUw);
  cudaGetSymbolAddress((void**)&wfcw, g_w_fcw);
  cudaGetSymbolAddress((void**)&w0ih, g_w_g0wih);
  cudaGetSymbolAddress((void**)&w0hh, g_w_g0whh);
  cudaGetSymbolAddress((void**)&w1ih, g_w_g1wih);
  cudaGetSymbolAddress((void**)&w1hh, g_w_g1whh);
  cudaGetSymbolAddress((void**)&xg,   g_xg);
  cudaGetSymbolAddress((void**)&xs,   g_xs);
  cudaGetSymbolAddress((void**)&ys,   g_ys);
  cudaGetSymbolAddress((void**)&y0,   g_y0);
  cudaGetSymbolAddress((void**)&h0b,  g_h0buf);
  cudaGetSymbolAddress((void**)&h1b,  g_h1buf);
  cudaGetSymbolAddress((void**)&gp,   g_gp);
  cudaGetSymbolAddress((void**)&fp,   g_fp);
  cudaGetSymbolAddress((void**)&Up,   g_Up);
  cudaGetSymbolAddress((void**)&ctx,  g_ctx);
  cudaGetSymbolAddress((void**)&lg,   g_lg);
  cudaGetSymbolAddress((void**)&nll,  g_nll);
  cudaGetSymbolAddress((void**)&msk,  g_msk);

  const size_t GSZ = (size_t)BB*3*HH;
  float* GP[4] = {gp, gp+GSZ, gp+2*GSZ, gp+3*GSZ};
  float* FP[4] = {fp, fp+BH, fp+2*BH, fp+3*BH};
  float* UP[2] = {Up, Up+BH};
  float* LG[2] = {lg, lg+(size_t)NTOK*VV};

  // one-time precompute
  k_inith<<<(BH+255)/256, 256>>>(inis, h0b, h1b);
  k_embed<<<(TT*BH+255)/256, 256>>>(emb, seq, xs);
  k_tobf16<<<(BB*CC*NL/4+255)/256, 256>>>(enc, ench, BB*CC*NL/4);
  k_tobf16<<<(HH*CC/4+255)/256, 256>>>(aWw, waWw, HH*CC/4);
  k_tobf16<<<(HH*HH/4+255)/256, 256>>>(aUw, waUw, HH*HH/4);
  k_tobf16<<<(HH*(CC+HH)/4+255)/256, 256>>>(fcw, wfcw, HH*(CC+HH)/4);
  k_tobf16<<<(3*HH*2*HH/4+255)/256, 256>>>(g0wih, w0ih, 3*HH*2*HH/4);
  k_tobf16<<<(3*HH*HH/4+255)/256, 256>>>(g0whh, w0hh, 3*HH*HH/4);
  k_tobf16<<<(3*HH*HH/4+255)/256, 256>>>(g1wih, w1ih, 3*HH*HH/4);
  k_tobf16<<<(3*HH*HH/4+255)/256, 256>>>(g1whh, w1hh, 3*HH*HH/4);
  // Ws = enc^T @ aWw^T + b  (bf16 mma, bf16 out)
  k_wsT<<<dim3(512, 4), 256>>>(enc, waWw, aWb, Wsh);
  // xg = xs @ g0wih[:,512:]^T  (single set, full K)
  k_mmT<<<dim3(92, 12, 1), 256>>>(xs, 512, w0ih, 1024, 512,
                                  xs, 512, w0ih, 1024, 512,
                                  1, 512, xg, 3*HH);

  auto attn_fc = [&](const float* h1cur, float* yout){
    k_mmT<<<dim3(4, 4, 2), 256>>>(h1cur, HH, waUw, 512, 0,
                                  h1cur, HH, waUw, 512, 0,
                                  2, 256, Up, HH);
    k_attn<<<BB, 256>>>(Wsh, ench, UP[0], UP[1], aUb, avw, avb, ctx);
    k_mmT<<<dim3(4, 4, 4), 256>>>(ctx, CC, wfcw, 1024, 0,
                                  h1cur, HH, wfcw, 1024, 512,
                                  2, 256, fp, HH);
    k_pwfc<<<BH/256, 256>>>(FP[0], FP[1], FP[2], FP[3], fcb, yout);
  };

  // y0
  attn_fc(h1b, y0);

  const float* yprev = y0;
  for (int t = 0; t < TT; t++){
    float* h0r = h0b + (size_t)(t & 1)*BH;
    float* h0w = h0b + (size_t)((t+1) & 1)*BH;
    float* h1r = h1b + (size_t)(t & 1)*BH;
    float* h1w = h1b + (size_t)((t+1) & 1)*BH;
    // GRU0: set0 y_prev @ wih[:, :512], set1 h0prev @ whh (each K=512, 2 slices)
    k_mmT<<<dim3(4, 12, 4), 256>>>(yprev, HH, w0ih, 1024, 0,
                                   h0r, HH, w0hh, 512, 0,
                                   2, 256, gp, 3*HH);
    k_pw<<<BH/256, 256>>>(GP[0], GP[1], GP[2], GP[3],
                          xg + (size_t)t*GSZ, h0r, g0bih, g0bhh, h0w);
    // GRU1
    k_mmT<<<dim3(4, 12, 4), 256>>>(h0w, HH, w1ih, 512, 0,
                                   h1r, HH, w1hh, 512, 0,
                                   2, 256, gp, 3*HH);
    k_pw<<<BH/256, 256>>>(GP[0], GP[1], GP[2], GP[3],
                          (const float*)nullptr, h1r, g1bih, g1bhh, h1w);
    // attention + out_proj
    attn_fc(h1w, ys + (size_t)t*BH);
    yprev = ys + (size_t)t*BH;
  }

  // logits (fp32) + NLL + reduce
  k_g64<<<dim3(92, 1, 2), 256>>>(ys, HH, clsw, 512, 0, LG[0], LG[1], VV);
  k_nll<<<NTOK/256, 256>>>(LG[0], LG[1], clsb, seq, nll, msk);
  k_reduce<<<1, 256>>>(nll, msk, (float*)d_out);
}